// round 1
// baseline (speedup 1.0000x reference)
#include <cuda_runtime.h>

#define IN_FEATURES 212445
#define N1 65536
#define N2 16384
#define NBINS 128
#define NCLS 20
#define BATCH 32

#define ACC_THREADS 64
#define ACC_CHUNKS 24

// ---------------- device scratch (no allocation allowed) ----------------
__device__ unsigned char g_m8[IN_FEATURES];     // composed map i -> bin (0..127)
__device__ float g_cnt1[N2];                    // |p1^-1(k)|
__device__ float g_cc1[NBINS];                  // segsum of cnt1 over p2
__device__ float g_cnt2[NBINS];                 // |p2^-1(m)|
__device__ float g_t2[BATCH * NBINS];           // 32x128 segment sums of x
__device__ float g_G[NCLS * NBINS];             // folded FC weights
__device__ float g_K[NCLS];                     // folded constants

// ---------------- setup kernels ----------------
__global__ void zero_kernel() {
    int i = blockIdx.x * blockDim.x + threadIdx.x;
    if (i < N2) g_cnt1[i] = 0.f;
    if (i < BATCH * NBINS) g_t2[i] = 0.f;
    if (i < NBINS) { g_cc1[i] = 0.f; g_cnt2[i] = 0.f; }
}

__global__ void compose_kernel(const int* __restrict__ p0,
                               const int* __restrict__ p1,
                               const int* __restrict__ p2) {
    int i = blockIdx.x * blockDim.x + threadIdx.x;
    if (i < IN_FEATURES) {
        g_m8[i] = (unsigned char)p2[p1[p0[i]]];
    }
}

__global__ void count1_kernel(const int* __restrict__ p1) {
    int j = blockIdx.x * blockDim.x + threadIdx.x;
    if (j < N1) atomicAdd(&g_cnt1[p1[j]], 1.0f);
}

__global__ void count2_kernel(const int* __restrict__ p2) {
    __shared__ float s_cc1[NBINS], s_cnt2[NBINS];
    int t = threadIdx.x;
    if (t < NBINS) { s_cc1[t] = 0.f; s_cnt2[t] = 0.f; }
    __syncthreads();
    int k = blockIdx.x * blockDim.x + t;
    if (k < N2) {
        int m = p2[k];
        atomicAdd(&s_cc1[m], g_cnt1[k]);
        atomicAdd(&s_cnt2[m], 1.0f);
    }
    __syncthreads();
    if (t < NBINS) {
        atomicAdd(&g_cc1[t], s_cc1[t]);
        atomicAdd(&g_cnt2[t], s_cnt2[t]);
    }
}

// Fold weights: A = W2@(W1@W0), B = W2@(W1@b0), C = W2@b1;
// G[cls,m] = sum_c3 fc_w[cls, c3*128+m] * A[c3]
// K[cls]   = fc_b[cls] + sum_m (Gb*cc1[m] + Gc*cnt2[m] + Gd)
__global__ void gk_kernel(const float* __restrict__ W0, const float* __restrict__ b0,
                          const float* __restrict__ W1, const float* __restrict__ b1,
                          const float* __restrict__ W2, const float* __restrict__ b2,
                          const float* __restrict__ fcw, const float* __restrict__ fcb) {
    __shared__ float u[64], v[64];
    __shared__ float A[128], B[128], C[128];
    __shared__ float red[128];
    int t = threadIdx.x;
    int cls = blockIdx.x;
    if (t < 64) {
        float su = 0.f, sv = 0.f;
        for (int c = 0; c < 32; c++) {
            float w = W1[t * 32 + c];
            su += w * W0[c];
            sv += w * b0[c];
        }
        u[t] = su; v[t] = sv;
    }
    __syncthreads();
    {
        float sa = 0.f, sb = 0.f, sc = 0.f;
        for (int c2 = 0; c2 < 64; c2++) {
            float w = W2[t * 64 + c2];
            sa += w * u[c2]; sb += w * v[c2]; sc += w * b1[c2];
        }
        A[t] = sa; B[t] = sb; C[t] = sc;
    }
    __syncthreads();
    int m = t;
    float gA = 0.f, gB = 0.f, gC = 0.f, gD = 0.f;
    for (int c3 = 0; c3 < 128; c3++) {
        float w = fcw[cls * (128 * NBINS) + c3 * NBINS + m];
        gA += w * A[c3]; gB += w * B[c3]; gC += w * C[c3]; gD += w * b2[c3];
    }
    g_G[cls * NBINS + m] = gA;
    red[m] = gB * g_cc1[m] + gC * g_cnt2[m] + gD;
    __syncthreads();
    for (int s = 64; s > 0; s >>= 1) {
        if (m < s) red[m] += red[m + s];
        __syncthreads();
    }
    if (m == 0) g_K[cls] = fcb[cls] + red[0];
}

// ---------------- main accumulation: t2[n,m] = segsum(x[n,:], m8) ----------------
// Per-thread private bins, layout bins[bin*64 + tid]: RMW bank = tid%32 -> conflict-free.
// Reduction with rotated start (l+t)&63 -> conflict-free column reads.
__global__ void __launch_bounds__(ACC_THREADS) accum_kernel(const float* __restrict__ x) {
    __shared__ float bins[NBINS * ACC_THREADS];  // 32 KB
    int t = threadIdx.x;
    int row = blockIdx.y;
    #pragma unroll
    for (int b = 0; b < NBINS; b++) bins[b * ACC_THREADS + t] = 0.f;

    const float* xr = x + (long)row * IN_FEATURES;
    const int chunk = (IN_FEATURES + ACC_CHUNKS - 1) / ACC_CHUNKS;
    int start = blockIdx.x * chunk;
    int end = min(start + chunk, IN_FEATURES);

    int i = start + t;
    for (; i + 3 * ACC_THREADS < end; i += 4 * ACC_THREADS) {
        float v0 = xr[i];
        float v1 = xr[i + ACC_THREADS];
        float v2 = xr[i + 2 * ACC_THREADS];
        float v3 = xr[i + 3 * ACC_THREADS];
        int m0 = g_m8[i];
        int m1 = g_m8[i + ACC_THREADS];
        int m2 = g_m8[i + 2 * ACC_THREADS];
        int m3 = g_m8[i + 3 * ACC_THREADS];
        bins[m0 * ACC_THREADS + t] += v0;
        bins[m1 * ACC_THREADS + t] += v1;
        bins[m2 * ACC_THREADS + t] += v2;
        bins[m3 * ACC_THREADS + t] += v3;
    }
    for (; i < end; i += ACC_THREADS) {
        bins[(int)g_m8[i] * ACC_THREADS + t] += xr[i];
    }
    __syncthreads();

    for (int b = t; b < NBINS; b += ACC_THREADS) {
        float s = 0.f;
        #pragma unroll 8
        for (int l = 0; l < ACC_THREADS; l++) {
            int lc = (l + t) & (ACC_THREADS - 1);
            s += bins[b * ACC_THREADS + lc];
        }
        atomicAdd(&g_t2[row * NBINS + b], s);
    }
}

// ---------------- final logits: out[n,cls] = G[cls,:] . t2[n,:] + K[cls] ----------------
__global__ void logits_kernel(float* __restrict__ out) {
    int t = blockIdx.x * blockDim.x + threadIdx.x;
    if (t >= BATCH * NCLS) return;
    int n = t / NCLS, cls = t % NCLS;
    float s = g_K[cls];
    const float* Gr = &g_G[cls * NBINS];
    const float* tr = &g_t2[n * NBINS];
    #pragma unroll 8
    for (int m = 0; m < NBINS; m++) s += Gr[m] * tr[m];
    out[t] = s;
}

// ---------------- launch ----------------
extern "C" void kernel_launch(void* const* d_in, const int* in_sizes, int n_in,
                              void* d_out, int out_size) {
    const float* x   = (const float*)d_in[0];
    const float* W0  = (const float*)d_in[1];
    const float* b0  = (const float*)d_in[2];
    const float* W1  = (const float*)d_in[3];
    const float* b1  = (const float*)d_in[4];
    const float* W2  = (const float*)d_in[5];
    const float* b2  = (const float*)d_in[6];
    const float* fcw = (const float*)d_in[7];
    const float* fcb = (const float*)d_in[8];
    const int*   p0  = (const int*)d_in[9];
    const int*   p1  = (const int*)d_in[10];
    const int*   p2  = (const int*)d_in[11];
    float* out = (float*)d_out;

    zero_kernel<<<64, 256>>>();
    compose_kernel<<<(IN_FEATURES + 255) / 256, 256>>>(p0, p1, p2);
    count1_kernel<<<N1 / 256, 256>>>(p1);
    count2_kernel<<<N2 / 256, 256>>>(p2);
    gk_kernel<<<NCLS, 128>>>(W0, b0, W1, b1, W2, b2, fcw, fcb);
    dim3 ag(ACC_CHUNKS, BATCH);
    accum_kernel<<<ag, ACC_THREADS>>>(x);
    logits_kernel<<<1, BATCH * NCLS>>>(out);
}

// round 2
// speedup vs baseline: 1.5892x; 1.5892x over previous
#include <cuda_runtime.h>

#define IN_FEATURES 212445
#define N1 65536
#define N2 16384
#define NBINS 128
#define NCLS 20
#define BATCH 32

#define ACC_THREADS 64
#define ACC_CHUNKS 24
#define NGROUPS ((IN_FEATURES + 3) / 4)   // 53112 groups of 4 features

// ---------------- device scratch (no allocation allowed) ----------------
// One contiguous zeroed block: [t2 (32*128)] [cc1 (128)] [cnt2 (128)]
__device__ float g_zeroed[BATCH * NBINS + 2 * NBINS];
#define G_T2   (g_zeroed)
#define G_CC1  (g_zeroed + BATCH * NBINS)
#define G_CNT2 (g_zeroed + BATCH * NBINS + NBINS)

__device__ unsigned char g_m8[NGROUPS * 4];   // composed map i -> bin, 4B-aligned padded

// ---------------- K1: compose map + histograms ----------------
// (a) g_m8[i] = p2[p1[p0[i]]]
// (b) cc1[m]  = |{ j in [0,N1) : p2[p1[j]] == m }|   (= segsum of cnt1 over p2)
// (c) cnt2[m] = |{ k in [0,N2) : p2[k] == m }|
__global__ void setup_kernel(const int* __restrict__ p0,
                             const int* __restrict__ p1,
                             const int* __restrict__ p2) {
    __shared__ float s_cc1[NBINS], s_cnt2[NBINS];
    int t = threadIdx.x;
    if (t < NBINS) { s_cc1[t] = 0.f; s_cnt2[t] = 0.f; }
    __syncthreads();

    int gid = blockIdx.x * blockDim.x + t;
    int stride = gridDim.x * blockDim.x;

    // compose (unrolled grid-stride for MLP)
    for (int i = gid; i < IN_FEATURES; i += stride) {
        g_m8[i] = (unsigned char)p2[p1[p0[i]]];
    }
    // pad tail groups deterministically (bin 0, values are guarded anyway)
    if (gid >= IN_FEATURES && gid < NGROUPS * 4) g_m8[gid] = 0;

    // cc1 histogram over p2 o p1
    for (int j = gid; j < N1; j += stride) {
        atomicAdd(&s_cc1[p2[p1[j]]], 1.0f);
    }
    // cnt2 histogram over p2
    for (int k = gid; k < N2; k += stride) {
        atomicAdd(&s_cnt2[p2[k]], 1.0f);
    }
    __syncthreads();
    if (t < NBINS) {
        if (s_cc1[t] != 0.f)  atomicAdd(&G_CC1[t], s_cc1[t]);
        if (s_cnt2[t] != 0.f) atomicAdd(&G_CNT2[t], s_cnt2[t]);
    }
}

// ---------------- K2: main accumulation t2[n,m] = segsum(x[n,:], m8) ----------------
// Per-thread private bins, layout bins[bin*64 + tid]: RMW bank = tid%32 -> conflict-free.
__global__ void __launch_bounds__(ACC_THREADS) accum_kernel(const float* __restrict__ x) {
    __shared__ float bins[NBINS * ACC_THREADS];  // 32 KB
    int t = threadIdx.x;
    int row = blockIdx.y;
    #pragma unroll
    for (int b = 0; b < NBINS; b++) bins[b * ACC_THREADS + t] = 0.f;

    const float* xr = x + (long)row * IN_FEATURES;
    const unsigned int* m8p = (const unsigned int*)g_m8;

    const int gchunk = (NGROUPS + ACC_CHUNKS - 1) / ACC_CHUNKS;
    int gstart = blockIdx.x * gchunk;
    int gend = min(gstart + gchunk, NGROUPS);

    for (int g = gstart + t; g < gend; g += ACC_THREADS) {
        unsigned int pack = m8p[g];
        int i = g * 4;
        if (i + 3 < IN_FEATURES) {
            float v0 = xr[i + 0];
            float v1 = xr[i + 1];
            float v2 = xr[i + 2];
            float v3 = xr[i + 3];
            bins[(int)(pack & 0xFF)         * ACC_THREADS + t] += v0;
            bins[(int)((pack >> 8)  & 0xFF) * ACC_THREADS + t] += v1;
            bins[(int)((pack >> 16) & 0xFF) * ACC_THREADS + t] += v2;
            bins[(int)(pack >> 24)          * ACC_THREADS + t] += v3;
        } else {
            #pragma unroll
            for (int k = 0; k < 4; k++) {
                int ii = i + k;
                if (ii < IN_FEATURES) {
                    int m = (pack >> (8 * k)) & 0xFF;
                    bins[m * ACC_THREADS + t] += xr[ii];
                }
            }
        }
    }
    __syncthreads();

    // reduce 64 private columns per bin; rotated start -> conflict-free
    for (int b = t; b < NBINS; b += ACC_THREADS) {
        float s = 0.f;
        #pragma unroll 8
        for (int l = 0; l < ACC_THREADS; l++) {
            int lc = (l + t) & (ACC_THREADS - 1);
            s += bins[b * ACC_THREADS + lc];
        }
        atomicAdd(&G_T2[row * NBINS + b], s);
    }
}

// ---------------- K3: fold weights + logits ----------------
// Per class (block): A = W2@(W1@W0), B = W2@(W1@b0), C = W2@b1
// G[m] = sum_c3 fcw[cls, c3*128+m]*A[c3]
// K    = fcb[cls] + sum_m (gB*cc1[m] + gC*cnt2[m] + gD)
// out[n,cls] = K + sum_m G[m]*t2[n,m]
__global__ void __launch_bounds__(128) finish_kernel(
        const float* __restrict__ W0, const float* __restrict__ b0,
        const float* __restrict__ W1, const float* __restrict__ b1,
        const float* __restrict__ W2, const float* __restrict__ b2,
        const float* __restrict__ fcw, const float* __restrict__ fcb,
        float* __restrict__ out) {
    __shared__ float u[64], v[64];
    __shared__ float A[128], B[128], C[128];
    __shared__ float sG[128];
    __shared__ float red[128];
    __shared__ float sK;

    int t = threadIdx.x;
    int cls = blockIdx.x;

    if (t < 64) {
        float su = 0.f, sv = 0.f;
        #pragma unroll 8
        for (int c = 0; c < 32; c++) {
            float w = W1[t * 32 + c];
            su += w * W0[c];
            sv += w * b0[c];
        }
        u[t] = su; v[t] = sv;
    }
    __syncthreads();
    {
        float sa = 0.f, sb = 0.f, sc = 0.f;
        #pragma unroll 8
        for (int c2 = 0; c2 < 64; c2++) {
            float w = W2[t * 64 + c2];
            sa += w * u[c2]; sb += w * v[c2]; sc += w * b1[c2];
        }
        A[t] = sa; B[t] = sb; C[t] = sc;
    }
    __syncthreads();
    int m = t;
    float gA = 0.f, gB = 0.f, gC = 0.f, gD = 0.f;
    const float* fr = fcw + (long)cls * (128 * NBINS) + m;
    #pragma unroll 8
    for (int c3 = 0; c3 < 128; c3++) {
        float w = fr[c3 * NBINS];
        gA += w * A[c3]; gB += w * B[c3]; gC += w * C[c3]; gD += w * b2[c3];
    }
    sG[m] = gA;
    red[m] = gB * G_CC1[m] + gC * G_CNT2[m] + gD;
    __syncthreads();
    #pragma unroll
    for (int s = 64; s > 0; s >>= 1) {
        if (m < s) red[m] += red[m + s];
        __syncthreads();
    }
    if (m == 0) sK = fcb[cls] + red[0];
    __syncthreads();

    // logits: 4 warps x 8 rows, shuffle reduction over 128 bins
    int wid = t >> 5, lid = t & 31;
    float K = sK;
    float g0 = sG[lid], g1 = sG[lid + 32], g2 = sG[lid + 64], g3 = sG[lid + 96];
    for (int n = wid * 8; n < wid * 8 + 8; n++) {
        const float* tr = &G_T2[n * NBINS];
        float s = g0 * tr[lid] + g1 * tr[lid + 32] + g2 * tr[lid + 64] + g3 * tr[lid + 96];
        #pragma unroll
        for (int off = 16; off > 0; off >>= 1)
            s += __shfl_xor_sync(0xFFFFFFFFu, s, off);
        if (lid == 0) out[n * NCLS + cls] = s + K;
    }
}

// ---------------- launch ----------------
extern "C" void kernel_launch(void* const* d_in, const int* in_sizes, int n_in,
                              void* d_out, int out_size) {
    const float* x   = (const float*)d_in[0];
    const float* W0  = (const float*)d_in[1];
    const float* b0  = (const float*)d_in[2];
    const float* W1  = (const float*)d_in[3];
    const float* b1  = (const float*)d_in[4];
    const float* W2  = (const float*)d_in[5];
    const float* b2  = (const float*)d_in[6];
    const float* fcw = (const float*)d_in[7];
    const float* fcb = (const float*)d_in[8];
    const int*   p0  = (const int*)d_in[9];
    const int*   p1  = (const int*)d_in[10];
    const int*   p2  = (const int*)d_in[11];
    float* out = (float*)d_out;

    void* zp = nullptr;
    cudaGetSymbolAddress(&zp, g_zeroed);
    cudaMemsetAsync(zp, 0, sizeof(float) * (BATCH * NBINS + 2 * NBINS));

    setup_kernel<<<208, 256>>>(p0, p1, p2);

    dim3 ag(ACC_CHUNKS, BATCH);
    accum_kernel<<<ag, ACC_THREADS>>>(x);

    finish_kernel<<<NCLS, 128>>>(W0, b0, W1, b1, W2, b2, fcw, fcb, out);
}

// round 3
// speedup vs baseline: 1.9392x; 1.2202x over previous
#include <cuda_runtime.h>

#define IN_FEATURES 212445
#define N1 65536
#define N2 16384
#define NBINS 128
#define NCLS 20
#define BATCH 32

#define ACC_THREADS 64
#define ACC_CHUNKS 28
#define NGROUPS ((IN_FEATURES + 3) / 4)   // 53112 groups of 4 features

// ---------------- device scratch (no allocation allowed) ----------------
// One contiguous zeroed block: [t2 (32*128)] [cc1 (128)] [cnt2 (128)]
__device__ float g_zeroed[BATCH * NBINS + 2 * NBINS];
#define G_T2   (g_zeroed)
#define G_CC1  (g_zeroed + BATCH * NBINS)
#define G_CNT2 (g_zeroed + BATCH * NBINS + NBINS)

__device__ unsigned int g_m8[NGROUPS];   // composed map, 4 bins packed per uint

// ---------------- K1: compose map + histograms ----------------
// grid = 256 blocks x 256 threads (covers max(NGROUPS, N1) in one pass)
__global__ void __launch_bounds__(256) setup_kernel(const int* __restrict__ p0,
                                                    const int* __restrict__ p1,
                                                    const int* __restrict__ p2) {
    __shared__ float s_cc1[NBINS], s_cnt2[NBINS];
    int t = threadIdx.x;
    if (t < NBINS) { s_cc1[t] = 0.f; s_cnt2[t] = 0.f; }
    __syncthreads();

    int gid = blockIdx.x * 256 + t;

    // compose: 4 features per thread, MLP=4 independent gather chains
    if (gid < NGROUPS) {
        int base = gid * 4;
        unsigned int pack;
        if (base + 3 < IN_FEATURES) {
            int4 a = ((const int4*)p0)[gid];
            int j0 = p1[a.x], j1 = p1[a.y], j2 = p1[a.z], j3 = p1[a.w];
            unsigned int m0 = p2[j0], m1 = p2[j1], m2 = p2[j2], m3 = p2[j3];
            pack = m0 | (m1 << 8) | (m2 << 16) | (m3 << 24);
        } else {
            pack = 0;
            for (int c = 0; c < 4; c++)
                if (base + c < IN_FEATURES)
                    pack |= ((unsigned int)p2[p1[p0[base + c]]]) << (8 * c);
        }
        g_m8[gid] = pack;
    }

    // cc1[m] = |{ j : p2[p1[j]] == m }|, cnt2[m] = |{ k : p2[k] == m }|
    if (gid < N1) atomicAdd(&s_cc1[p2[p1[gid]]], 1.0f);
    if (gid < N2) atomicAdd(&s_cnt2[p2[gid]], 1.0f);
    __syncthreads();
    if (t < NBINS) {
        if (s_cc1[t] != 0.f)  atomicAdd(&G_CC1[t], s_cc1[t]);
        if (s_cnt2[t] != 0.f) atomicAdd(&G_CNT2[t], s_cnt2[t]);
    }
}

// ---------------- K2: main accumulation t2[n,m] = segsum(x[n,:], map) ----------------
// float4 aligned x loads; bin bytes via funnel-shift of packed map.
// Per-thread private bins, layout bins[bin*64 + tid]: RMW bank = tid%32 -> conflict-free.
__global__ void __launch_bounds__(ACC_THREADS) accum_kernel(const float* __restrict__ x) {
    __shared__ float bins[NBINS * ACC_THREADS];  // 32 KB
    int t = threadIdx.x;
    int c = blockIdx.x;
    int r = blockIdx.y;
    #pragma unroll
    for (int b = 0; b < NBINS; b++) bins[b * ACC_THREADS + t] = 0.f;

    const float* xr = x + (size_t)r * IN_FEATURES;
    // IN_FEATURES % 4 == 1, so address of xr[f] is 16B-aligned when f == p (mod 4):
    int p = (4 - (r & 3)) & 3;
    int Kv = (IN_FEATURES - p) >> 2;           // number of aligned float4 vectors
    int ck = (Kv + ACC_CHUNKS - 1) / ACC_CHUNKS;
    int k0 = c * ck;
    int k1 = min(k0 + ck, Kv);

    const unsigned int* mu = g_m8;
    const float4* xv = (const float4*)(xr + p);
    int sh = 8 * p;

    for (int k = k0 + t; k < k1; k += ACC_THREADS) {
        unsigned int u0 = mu[k];
        unsigned int u1 = mu[k + 1];               // safe: k+1 <= Kv < NGROUPS
        unsigned int b = __funnelshift_r(u0, u1, sh);   // bytes p+4k .. p+4k+3
        float4 X = xv[k];
        bins[(int)(b & 255u)         * ACC_THREADS + t] += X.x;
        bins[(int)((b >> 8) & 255u)  * ACC_THREADS + t] += X.y;
        bins[(int)((b >> 16) & 255u) * ACC_THREADS + t] += X.z;
        bins[(int)(b >> 24)          * ACC_THREADS + t] += X.w;
    }

    // head [0, p) handled by chunk 0; tail by last chunk
    const unsigned char* m8b = (const unsigned char*)g_m8;
    if (c == 0 && t < p) {
        bins[(int)m8b[t] * ACC_THREADS + t] += xr[t];
    }
    int tail0 = p + 4 * Kv;
    int ntail = IN_FEATURES - tail0;
    if (c == ACC_CHUNKS - 1 && t < ntail) {
        bins[(int)m8b[tail0 + t] * ACC_THREADS + t] += xr[tail0 + t];
    }
    __syncthreads();

    // reduce 64 private columns per bin; rotated start -> conflict-free
    for (int b = t; b < NBINS; b += ACC_THREADS) {
        float s = 0.f;
        #pragma unroll 8
        for (int l = 0; l < ACC_THREADS; l++) {
            int lc = (l + t) & (ACC_THREADS - 1);
            s += bins[b * ACC_THREADS + lc];
        }
        atomicAdd(&G_T2[r * NBINS + b], s);
    }
}

// ---------------- K3: fold weights + logits ----------------
__global__ void __launch_bounds__(128) finish_kernel(
        const float* __restrict__ W0, const float* __restrict__ b0,
        const float* __restrict__ W1, const float* __restrict__ b1,
        const float* __restrict__ W2, const float* __restrict__ b2,
        const float* __restrict__ fcw, const float* __restrict__ fcb,
        float* __restrict__ out) {
    __shared__ float u[64], v[64];
    __shared__ float A[128], B[128], C[128];
    __shared__ float sG[128];
    __shared__ float red[128];
    __shared__ float sK;

    int t = threadIdx.x;
    int cls = blockIdx.x;

    if (t < 64) {
        float su = 0.f, sv = 0.f;
        #pragma unroll 8
        for (int cc = 0; cc < 32; cc++) {
            float w = W1[t * 32 + cc];
            su += w * W0[cc];
            sv += w * b0[cc];
        }
        u[t] = su; v[t] = sv;
    }
    __syncthreads();
    {
        float sa = 0.f, sb = 0.f, sc = 0.f;
        #pragma unroll 8
        for (int c2 = 0; c2 < 64; c2++) {
            float w = W2[t * 64 + c2];
            sa += w * u[c2]; sb += w * v[c2]; sc += w * b1[c2];
        }
        A[t] = sa; B[t] = sb; C[t] = sc;
    }
    __syncthreads();
    int m = t;
    float gA = 0.f, gB = 0.f, gC = 0.f, gD = 0.f;
    const float* fr = fcw + (size_t)cls * (128 * NBINS) + m;
    #pragma unroll 8
    for (int c3 = 0; c3 < 128; c3++) {
        float w = fr[c3 * NBINS];
        gA += w * A[c3]; gB += w * B[c3]; gC += w * C[c3]; gD += w * b2[c3];
    }
    sG[m] = gA;
    red[m] = gB * G_CC1[m] + gC * G_CNT2[m] + gD;
    __syncthreads();
    #pragma unroll
    for (int s = 64; s > 0; s >>= 1) {
        if (m < s) red[m] += red[m + s];
        __syncthreads();
    }
    if (m == 0) sK = fcb[cls] + red[0];
    __syncthreads();

    // logits: 4 warps x 8 rows, shuffle reduction over 128 bins
    int wid = t >> 5, lid = t & 31;
    float K = sK;
    float g0 = sG[lid], g1 = sG[lid + 32], g2 = sG[lid + 64], g3 = sG[lid + 96];
    for (int n = wid * 8; n < wid * 8 + 8; n++) {
        const float* tr = &G_T2[n * NBINS];
        float s = g0 * tr[lid] + g1 * tr[lid + 32] + g2 * tr[lid + 64] + g3 * tr[lid + 96];
        #pragma unroll
        for (int off = 16; off > 0; off >>= 1)
            s += __shfl_xor_sync(0xFFFFFFFFu, s, off);
        if (lid == 0) out[n * NCLS + cls] = s + K;
    }
}

// ---------------- launch ----------------
extern "C" void kernel_launch(void* const* d_in, const int* in_sizes, int n_in,
                              void* d_out, int out_size) {
    const float* x   = (const float*)d_in[0];
    const float* W0  = (const float*)d_in[1];
    const float* b0  = (const float*)d_in[2];
    const float* W1  = (const float*)d_in[3];
    const float* b1  = (const float*)d_in[4];
    const float* W2  = (const float*)d_in[5];
    const float* b2  = (const float*)d_in[6];
    const float* fcw = (const float*)d_in[7];
    const float* fcb = (const float*)d_in[8];
    const int*   p0  = (const int*)d_in[9];
    const int*   p1  = (const int*)d_in[10];
    const int*   p2  = (const int*)d_in[11];
    float* out = (float*)d_out;

    void* zp = nullptr;
    cudaGetSymbolAddress(&zp, g_zeroed);
    cudaMemsetAsync(zp, 0, sizeof(float) * (BATCH * NBINS + 2 * NBINS));

    setup_kernel<<<256, 256>>>(p0, p1, p2);

    dim3 ag(ACC_CHUNKS, BATCH);
    accum_kernel<<<ag, ACC_THREADS>>>(x);

    finish_kernel<<<NCLS, 128>>>(W0, b0, W1, b1, W2, b2, fcw, fcb, out);
}